// round 13
// baseline (speedup 1.0000x reference)
#include <cuda_runtime.h>
#include <cuda_fp16.h>
#include <cstdint>

#define NS 512
#define NK 64
#define NVEC 65536
#define M_TILE 128
#define NCTA (NVEC / M_TILE)      /* 512 */
#define NTHR 256

#define OFF_Z      (NVEC*NK)
#define OFF_COMMIT (OFF_Z + NVEC)
#define OFF_CB     (OFF_COMMIT + 1)
#define OFF_ERR    (OFF_CB + 1)

/* dynamic smem: A region [0,32768) reused as B double-buffer after
   A fragments are register-resident. */
#define SM_A    0
#define SM_B    0
#define SM_SCN  32768       /* 512*4 */
#define SM_VN   34816       /* 128*4 */
#define SM_RED  35328       /* 8*4 */
#define SM_TOT  35392

__device__ float  g_c[NS * NK];
__device__ float  g_cnh[NS];
__device__ __half g_ch[2][NS * NK];      // codebook fp16 planes (h0, h1)
__device__ float  g_partial[NCTA];
__device__ int    g_done;

__device__ __forceinline__ uint32_t smem_u32(const void* p) {
    uint32_t a;
    asm("{ .reg .u64 t; cvta.to.shared.u64 t, %1; cvt.u32.u64 %0, t; }" : "=r"(a) : "l"(p));
    return a;
}
__device__ __forceinline__ void ldsm_x4(uint32_t* r, uint32_t a) {
    asm volatile("ldmatrix.sync.aligned.m8n8.x4.shared.b16 {%0,%1,%2,%3}, [%4];"
                 : "=r"(r[0]), "=r"(r[1]), "=r"(r[2]), "=r"(r[3]) : "r"(a));
}
// f32-accumulate MMA (main term)
__device__ __forceinline__ void mma_f32(float* c, const uint32_t* a, const uint32_t* b) {
    asm volatile("mma.sync.aligned.m16n8k16.row.col.f32.f16.f16.f32 "
                 "{%0,%1,%2,%3}, {%4,%5,%6,%7}, {%8,%9}, {%0,%1,%2,%3};"
                 : "+f"(c[0]), "+f"(c[1]), "+f"(c[2]), "+f"(c[3])
                 : "r"(a[0]), "r"(a[1]), "r"(a[2]), "r"(a[3]), "r"(b[0]), "r"(b[1]));
}
// f16-accumulate MMA (correction terms, ~2^-11 magnitude)
__device__ __forceinline__ void mma_f16(uint32_t* c, const uint32_t* a, const uint32_t* b) {
    asm volatile("mma.sync.aligned.m16n8k16.row.col.f16.f16.f16.f16 "
                 "{%0,%1}, {%2,%3,%4,%5}, {%6,%7}, {%0,%1};"
                 : "+r"(c[0]), "+r"(c[1])
                 : "r"(a[0]), "r"(a[1]), "r"(a[2]), "r"(a[3]), "r"(b[0]), "r"(b[1]));
}
__device__ __forceinline__ void cpa16(uint32_t dst, const void* src) {
    asm volatile("cp.async.cg.shared.global [%0], [%1], 16;" :: "r"(dst), "l"(src));
}
#define CPA_COMMIT() asm volatile("cp.async.commit_group;" ::: "memory")
#define CPA_WAIT(n)  asm volatile("cp.async.wait_group %0;" :: "n"(n) : "memory")

__device__ __forceinline__ void hsplit(float x, __half& h0, __half& h1) {
    h0 = __float2half_rn(x);
    h1 = __float2half_rn(x - __half2float(h0));
}

// ---------------------------------------------------------------------------
// Kernel 1: codebook -> fp32 + half-norms + fp16 planes; reset done counter.
// ---------------------------------------------------------------------------
__global__ void __launch_bounds__(128) vq_prep_code(const float* __restrict__ c_sum,
                                                    const float* __restrict__ c_count) {
    if (blockIdx.x == 0 && threadIdx.x == 0) g_done = 0;
    int warp = (blockIdx.x * blockDim.x + threadIdx.x) >> 5;
    int lane = threadIdx.x & 31;
    if (warp >= NS) return;
    float inv = 1.0f / fmaxf(c_count[warp], 0.01f);
    float a = c_sum[warp * NK + lane] * inv;
    float b = c_sum[warp * NK + 32 + lane] * inv;
    g_c[warp * NK + lane] = a;
    g_c[warp * NK + 32 + lane] = b;
    __half h0, h1;
    hsplit(a, h0, h1);
    g_ch[0][warp * NK + lane] = h0;
    g_ch[1][warp * NK + lane] = h1;
    hsplit(b, h0, h1);
    g_ch[0][warp * NK + 32 + lane] = h0;
    g_ch[1][warp * NK + 32 + lane] = h1;
    float nh = a * a + b * b;
#pragma unroll
    for (int o = 16; o; o >>= 1) nh += __shfl_xor_sync(0xffffffffu, nh, o);
    if (lane == 0) g_cnh[warp] = 0.5f * nh;
}

// ---------------------------------------------------------------------------
// Kernel 2: 256 threads, 8 warps, 16 rows/warp; main term f32-acc HMMA,
// correction terms (a1b0 + a0b1) f16-acc HMMA (double-rate path).
// ---------------------------------------------------------------------------
__global__ void __launch_bounds__(NTHR, 3) vq_mma(const float* __restrict__ vecs,
                                                  float* __restrict__ out) {
    extern __shared__ __align__(128) char smem[];
    uint32_t sb = smem_u32(smem);
    int tid = threadIdx.x;
    int wid = tid >> 5;
    int lane = tid & 31;
    int cta = blockIdx.x;

    for (int i = tid; i < NS; i += NTHR)
        reinterpret_cast<float*>(smem + SM_SCN)[i] = g_cnh[i];

    // fused A conversion: thread pair (2t, 2t+1) owns vector row t (half each)
    {
        int row = tid >> 1;
        int half = tid & 1;
        const float4* src = reinterpret_cast<const float4*>(
            vecs + ((size_t)cta * M_TILE + row) * NK) + half * 8;
        float vn = 0.f;
        int rsw = row & 7;
#pragma unroll
        for (int c = 0; c < 4; c++) {
            int ch = half * 4 + c;
            float4 q0 = src[2 * c], q1 = src[2 * c + 1];
            float x[8] = {q0.x, q0.y, q0.z, q0.w, q1.x, q1.y, q1.z, q1.w};
            union { uint4 u; __half2 h[4]; } p0, p1;
#pragma unroll
            for (int j = 0; j < 4; j++) {
                __half a0, a1, b0, b1;
                hsplit(x[2 * j], a0, a1);
                hsplit(x[2 * j + 1], b0, b1);
                p0.h[j] = __halves2half2(a0, b0);
                p1.h[j] = __halves2half2(a1, b1);
                vn += x[2 * j] * x[2 * j] + x[2 * j + 1] * x[2 * j + 1];
            }
            uint32_t off = row * 128 + ((ch ^ rsw) << 4);
            *reinterpret_cast<uint4*>(smem + SM_A + off) = p0.u;
            *reinterpret_cast<uint4*>(smem + SM_A + 16384 + off) = p1.u;
        }
        vn += __shfl_xor_sync(0xffffffffu, vn, 1);
        if (half == 0) reinterpret_cast<float*>(smem + SM_VN)[row] = vn;
    }
    __syncthreads();

    // register-resident A fragments: [plane][kstep][4] (warp owns 16 rows)
    uint32_t af[2][4][4];
    {
        int r = lane & 15;
        int hi = lane >> 4;
#pragma unroll
        for (int p = 0; p < 2; p++) {
            int row = wid * 16 + r;
#pragma unroll
            for (int k = 0; k < 4; k++) {
                int ch = (2 * k + hi) ^ (row & 7);
                ldsm_x4(af[p][k], sb + SM_A + p * 16384 + row * 128 + ch * 16);
            }
        }
    }
    __syncthreads();   // A region becomes B double-buffer

    auto loadB = [&](int tile, int buf) {
#pragma unroll
        for (int j = 0; j < 4; j++) {
            int i = tid + NTHR * j;
            int row = i >> 3, ch = i & 7;
            int p = row >> 6, r = row & 63;
            const __half* src = g_ch[p] + ((size_t)tile * 64 + r) * NK + ch * 8;
            cpa16(sb + SM_B + buf * 16384 + p * 8192 + r * 128 + (((ch ^ (r & 7))) << 4), src);
        }
    };
    loadB(0, 0);
    CPA_COMMIT();

    const float* scn = reinterpret_cast<const float*>(smem + SM_SCN);
    float best[2] = {-3.4e38f, -3.4e38f};
    int idx[2] = {0, 0};
    int brow_lo = (lane >> 4) << 3;
    int kh = (lane >> 3) & 1;

    for (int tile = 0; tile < 8; tile++) {
        if (tile < 7) { loadB(tile + 1, (tile + 1) & 1); CPA_COMMIT(); CPA_WAIT(1); }
        else CPA_WAIT(0);
        __syncthreads();
        uint32_t bbase = sb + SM_B + (tile & 1) * 16384;

#pragma unroll
        for (int npair = 0; npair < 4; npair++) {
            float    acc[2][4] = {};          // main term, f32 acc [nblock][4]
            uint32_t cor[2][2] = {};          // corrections, f16 acc [nblock][2]
            int row = npair * 16 + brow_lo + (lane & 7);
            int rsw = row & 7;
#pragma unroll
            for (int k = 0; k < 4; k++) {     // B plane 0: a0 (f32) + a1 (f16)
                uint32_t bf[4];
                ldsm_x4(bf, bbase + row * 128 + (((2 * k + kh) ^ rsw) << 4));
                mma_f32(acc[0], af[0][k], bf + 0);
                mma_f32(acc[1], af[0][k], bf + 2);
                mma_f16(cor[0], af[1][k], bf + 0);
                mma_f16(cor[1], af[1][k], bf + 2);
            }
#pragma unroll
            for (int k = 0; k < 4; k++) {     // B plane 1: a0 term (f16)
                uint32_t bf[4];
                ldsm_x4(bf, bbase + 8192 + row * 128 + (((2 * k + kh) ^ rsw) << 4));
                mma_f16(cor[0], af[0][k], bf + 0);
                mma_f16(cor[1], af[0][k], bf + 2);
            }
#pragma unroll
            for (int nb = 0; nb < 2; nb++) {
                int ncol = tile * 64 + npair * 16 + nb * 8 + 2 * (lane & 3);
                float s0 = scn[ncol], s1 = scn[ncol + 1];
                float2 c01 = __half22float2(*reinterpret_cast<__half2*>(&cor[nb][0]));
                float2 c23 = __half22float2(*reinterpret_cast<__half2*>(&cor[nb][1]));
                float v;
                v = acc[nb][0] + c01.x - s0; if (v > best[0]) { best[0] = v; idx[0] = ncol; }
                v = acc[nb][1] + c01.y - s1; if (v > best[0]) { best[0] = v; idx[0] = ncol + 1; }
                v = acc[nb][2] + c23.x - s0; if (v > best[1]) { best[1] = v; idx[1] = ncol; }
                v = acc[nb][3] + c23.y - s1; if (v > best[1]) { best[1] = v; idx[1] = ncol + 1; }
            }
        }
        __syncthreads();
    }

    // quad reduce (tie -> lower index)
#pragma unroll
    for (int slot = 0; slot < 2; slot++) {
#pragma unroll
        for (int off = 1; off <= 2; off <<= 1) {
            float ob = __shfl_xor_sync(0xffffffffu, best[slot], off);
            int oi = __shfl_xor_sync(0xffffffffu, idx[slot], off);
            if (ob > best[slot] || (ob == best[slot] && oi < idx[slot])) {
                best[slot] = ob; idx[slot] = oi;
            }
        }
    }

    const float* svn = reinterpret_cast<const float*>(smem + SM_VN);
    float errsum = 0.f;
#pragma unroll
    for (int slot = 0; slot < 2; slot++) {
        int row = wid * 16 + slot * 8 + (lane >> 2);
        int n = cta * M_TILE + row;
        const float4* c = reinterpret_cast<const float4*>(g_c + (size_t)idx[slot] * NK);
        float4* o = reinterpret_cast<float4*>(out + (size_t)n * NK);
#pragma unroll
        for (int j = lane & 3; j < 16; j += 4) o[j] = c[j];
        if ((lane & 3) == 0) {
            float err = fmaxf(svn[row] - 2.0f * best[slot], 0.0f);
            out[OFF_Z + n] = (float)idx[slot];
            out[OFF_ERR + n] = err;
            errsum += err;
        }
    }
#pragma unroll
    for (int o = 16; o; o >>= 1) errsum += __shfl_xor_sync(0xffffffffu, errsum, o);
    float* red = reinterpret_cast<float*>(smem + SM_RED);
    if (lane == 0) red[wid] = errsum;
    __syncthreads();
    if (tid == 0)
        g_partial[cta] = ((red[0] + red[1]) + (red[2] + red[3]))
                       + ((red[4] + red[5]) + (red[6] + red[7]));

    // fused finalize: last CTA reduces all partials (fixed deterministic order)
    __shared__ int s_last;
    if (tid == 0) {
        __threadfence();
        s_last = (atomicAdd(&g_done, 1) == NCTA - 1);
    }
    __syncthreads();
    if (s_last) {
        __threadfence();
        float* fred = reinterpret_cast<float*>(smem + SM_A);
        fred[tid] = g_partial[tid] + g_partial[tid + 256];
        __syncthreads();
#pragma unroll
        for (int off = 128; off > 0; off >>= 1) {
            if (tid < off) fred[tid] += fred[tid + off];
            __syncthreads();
        }
        if (tid == 0) {
            out[OFF_COMMIT] = fred[0] * (1.0f / (float)NVEC);
            out[OFF_CB] = 0.0f;   // l_codebook is identically 0 in forward value
        }
    }
}

extern "C" void kernel_launch(void* const* d_in, const int* in_sizes, int n_in,
                              void* d_out, int out_size) {
    const float* vecs    = (const float*)d_in[0];
    const float* c_sum   = (const float*)d_in[1];
    const float* c_count = (const float*)d_in[2];
    float* out = (float*)d_out;

    cudaFuncSetAttribute(vq_mma, cudaFuncAttributeMaxDynamicSharedMemorySize, SM_TOT);

    vq_prep_code<<<128, 128>>>(c_sum, c_count);
    vq_mma<<<NCTA, NTHR, SM_TOT>>>(vecs, out);
}